// round 11
// baseline (speedup 1.0000x reference)
#include <cuda_runtime.h>

#define NQ 2048
#define NO 2048
#define LAT 64
#define OSPLIT 16
#define QPW 4
#define NWARPS 8
#define QPB (QPW*NWARPS)      /* 32 queries per block */
#define THREADS (NWARPS*32)   /* 256 */
#define OPART (NO/OSPLIT)     /* 128 obs per block */
#define NCHUNK 4              /* 4 chunks of 32 within OPART */
#define L2E 1.4426950408889634f
#define NEGBIG (-1e30f)
#define FULLMASK 0xffffffffu

typedef unsigned long long u64;

// dynamic smem layout (bytes)
#define SV    0        /* float s_v[128*64]            32768 */
#define SBO   32768    /* float4 s_bo[4][16][32]       32768 (aliased by s_p after logits) */
#define SAQ   65536    /* float4 s_aq[32][16]           8192 */
#define SPOS  73728    /* float4 s_pos[128]             2048 */
#define SW2H  75776    /* float4 s_w2h[16]               256 */
#define SOC   76032    /* float  s_oc[128]               512 */
#define SQAC  76544    /* float  s_qac[32]               128 */
#define SMEM_BYTES 76672

// ---------------- packed f32x2 helpers ----------------
__device__ __forceinline__ void upk(u64 v, float& lo, float& hi) {
    asm("mov.b64 {%0,%1},%2;" : "=f"(lo), "=f"(hi) : "l"(v));
}
__device__ __forceinline__ u64 add2(u64 a, u64 b) {
    u64 d; asm("add.rn.f32x2 %0,%1,%2;" : "=l"(d) : "l"(a), "l"(b)); return d;
}
__device__ __forceinline__ u64 fma2(u64 a, u64 b, u64 c) {
    u64 d; asm("fma.rn.f32x2 %0,%1,%2,%3;" : "=l"(d) : "l"(a), "l"(b), "l"(c)); return d;
}

// ---------------- cp.async helpers ----------------
__device__ __forceinline__ void cpa16(void* smem, const void* g) {
    unsigned s = (unsigned)__cvta_generic_to_shared(smem);
    asm volatile("cp.async.cg.shared.global [%0], [%1], 16;" :: "r"(s), "l"(g));
}
#define CP_COMMIT() asm volatile("cp.async.commit_group;")
#define CP_WAIT0()  asm volatile("cp.async.wait_group 0;")

// ---------------- device scratch ----------------
__device__ float4 g_aq4[NQ*LAT/4];      // [q][l4]
__device__ float4 g_bo4[NO*LAT/4];      // interleaved [gchunk][l4][o_in32]
__device__ float4 g_v4[NO*LAT/4];       // [o][l4]
__device__ float4 g_pos4[NO];           // (x,y,z,0)
__device__ float  g_qac[NQ];            // sum_l w2h*aq
__device__ float  g_obc[NO];            // sum_l w2h*bo
__device__ float  g_w2h[LAT];           // W2*0.5
__device__ float  g_pacc[OSPLIT][NQ*LAT];
__device__ float  g_pm[OSPLIT][NQ];
__device__ float  g_ps[OSPLIT][NQ];

// ---------------- prep ----------------
__global__ __launch_bounds__(256)
void prep_kernel(const float* __restrict__ h_obs,
                 const float* __restrict__ pos_obs,
                 const float* __restrict__ pos_query,
                 const float* __restrict__ W1,
                 const float* __restrict__ b1,
                 const float* __restrict__ W2,
                 const float* __restrict__ Wv,
                 const float* __restrict__ bv)
{
    __shared__ float4 s_wv[64*16];   // 16KB (v branch)
    __shared__ float4 s_bv[16];
    __shared__ float  spa[8], spb[8];
    const int tid = threadIdx.x;
    const int blk = blockIdx.x;

    if (blk < 128) {
        const float4* wv4 = (const float4*)Wv;
#pragma unroll
        for (int i = 0; i < 4; i++) s_wv[i*256 + tid] = wv4[i*256 + tid];
        if (tid < 16) s_bv[tid] = ((const float4*)bv)[tid];
        __syncthreads();

        const int l4  = tid & 15;
        const int r   = tid >> 4;
        const int row = blk*16 + r;
        const float4* h4 = (const float4*)(h_obs + row*LAT);

        float4 a0 = s_bv[l4];
        float4 a1 = make_float4(0.f,0.f,0.f,0.f);
        float4 a2 = make_float4(0.f,0.f,0.f,0.f);
        float4 a3 = make_float4(0.f,0.f,0.f,0.f);
#pragma unroll
        for (int k4 = 0; k4 < 16; k4++) {
            float4 h = h4[k4];
            float4 w0 = s_wv[(4*k4+0)*16 + l4];
            float4 w1 = s_wv[(4*k4+1)*16 + l4];
            float4 w2 = s_wv[(4*k4+2)*16 + l4];
            float4 w3 = s_wv[(4*k4+3)*16 + l4];
            a0.x = fmaf(h.x, w0.x, a0.x); a0.y = fmaf(h.x, w0.y, a0.y);
            a0.z = fmaf(h.x, w0.z, a0.z); a0.w = fmaf(h.x, w0.w, a0.w);
            a1.x = fmaf(h.y, w1.x, a1.x); a1.y = fmaf(h.y, w1.y, a1.y);
            a1.z = fmaf(h.y, w1.z, a1.z); a1.w = fmaf(h.y, w1.w, a1.w);
            a2.x = fmaf(h.z, w2.x, a2.x); a2.y = fmaf(h.z, w2.y, a2.y);
            a2.z = fmaf(h.z, w2.z, a2.z); a2.w = fmaf(h.z, w2.w, a2.w);
            a3.x = fmaf(h.w, w3.x, a3.x); a3.y = fmaf(h.w, w3.y, a3.y);
            a3.z = fmaf(h.w, w3.z, a3.z); a3.w = fmaf(h.w, w3.w, a3.w);
        }
        float4 v;
        v.x = (a0.x + a1.x) + (a2.x + a3.x);
        v.y = (a0.y + a1.y) + (a2.y + a3.y);
        v.z = (a0.z + a1.z) + (a2.z + a3.z);
        v.w = (a0.w + a1.w) + (a2.w + a3.w);
        g_v4[row*16 + l4] = v;
    } else {
        int idx = (blk - 128)*256 + tid;     // covers NQ*LAT
        int row = idx >> 6;
        int l   = idx & 63;

        float a = 0.f;
        float b = b1[l];
#pragma unroll
        for (int e = 0; e < 3; e++) {
            float wc = W1[(6+e)*LAT + l];
            a = fmaf(pos_query[row*3 + e], W1[e*LAT + l] + wc, a);
            b = fmaf(pos_obs  [row*3 + e], W1[(3+e)*LAT + l] - wc, b);
        }
        ((float*)g_aq4)[row*LAT + l] = a;

        int ch = row >> 5, oin = row & 31, l4i = l >> 2, li = l & 3;
        ((float*)g_bo4)[(((ch*16) + l4i)*32 + oin)*4 + li] = b;

        if (l == 0)
            g_pos4[row] = make_float4(pos_obs[row*3], pos_obs[row*3+1], pos_obs[row*3+2], 0.f);

        // w2h-weighted row reductions
        float w2h = 0.5f * W2[l];
        float ta = w2h * a, tb = w2h * b;
#pragma unroll
        for (int off = 16; off > 0; off >>= 1) {
            ta += __shfl_xor_sync(FULLMASK, ta, off);
            tb += __shfl_xor_sync(FULLMASK, tb, off);
        }
        int wl = tid >> 5;
        if ((tid & 31) == 0) { spa[wl] = ta; spb[wl] = tb; }
        __syncthreads();
        if ((tid & 63) == 0) {
            g_qac[row] = spa[wl] + spa[wl+1];
            g_obc[row] = spb[wl] + spb[wl+1];
        }
        if (blk == 128 && tid < 64)
            g_w2h[tid] = 0.5f * W2[tid];
    }
}

// ---------------- main: fused masked-softmax attention ----------------
__global__ __launch_bounds__(THREADS, 3)
void main_kernel(const float* __restrict__ pos_query)
{
    extern __shared__ char sm[];
    const int tid   = threadIdx.x;
    const int warp  = tid >> 5;
    const int lane  = tid & 31;
    const int qblk  = blockIdx.x;        // 0..63
    const int split = blockIdx.y;        // 0..15
    const int obase = split * OPART;
    const int gch0  = obase / 32;

    // ---- prologue: one-shot async staging of all tiles ----
    {
        float4* sv = (float4*)(sm + SV);
        float4* sb = (float4*)(sm + SBO);
        const float4* gv = g_v4  + obase*16;
        const float4* gb = g_bo4 + gch0*512;
#pragma unroll
        for (int i = 0; i < 8; i++) {
            cpa16(&sv[i*THREADS + tid], &gv[i*THREADS + tid]);
            cpa16(&sb[i*THREADS + tid], &gb[i*THREADS + tid]);
        }
        float4* sa = (float4*)(sm + SAQ);
        const float4* ga = g_aq4 + qblk*QPB*16;
#pragma unroll
        for (int i = 0; i < 2; i++)
            cpa16(&sa[i*THREADS + tid], &ga[i*THREADS + tid]);
        if (tid < 128) cpa16(&((float4*)(sm + SPOS))[tid], &g_pos4[obase + tid]);
        if (tid < 16)  cpa16(&((float4*)(sm + SW2H))[tid], &((const float4*)g_w2h)[tid]);
        if (tid < 32)  cpa16((float*)(sm + SOC) + tid*4, &g_obc[obase + tid*4]);
        if (tid < 8)   cpa16((float*)(sm + SQAC) + tid*4, &g_qac[qblk*QPB + tid*4]);
        CP_COMMIT();
    }

    // per-warp query constants (broadcast global loads, L1/L2-resident)
    const int q0  = warp*QPW;
    const int gq0 = qblk*QPB + q0;
    float qpx[QPW], qpy[QPW], qpz[QPW];
#pragma unroll
    for (int q = 0; q < QPW; q++) {
        qpx[q] = pos_query[(gq0+q)*3 + 0];
        qpy[q] = pos_query[(gq0+q)*3 + 1];
        qpz[q] = pos_query[(gq0+q)*3 + 2];
    }

    CP_WAIT0();
    __syncthreads();

    // ---- logits for all 128 obs: LDS.128 as ulonglong2 (no pk MOVs) ----
    float lacc[QPW*NCHUNK];
#pragma unroll
    for (int i = 0; i < QPW*NCHUNK; i++) lacc[i] = 0.f;

    const ulonglong2* aqv  = (const ulonglong2*)(sm + SAQ);
    const ulonglong2* bov  = (const ulonglong2*)(sm + SBO);
    const float4*     w2h4 = (const float4*)(sm + SW2H);

#pragma unroll 1
    for (int l4 = 0; l4 < 16; l4++) {
        float4 w = w2h4[l4];
        u64 a01[QPW], a23[QPW];
#pragma unroll
        for (int q = 0; q < QPW; q++) {
            ulonglong2 av = aqv[(q0+q)*16 + l4];   // LDS.128 broadcast
            a01[q] = av.x;
            a23[q] = av.y;
        }
#pragma unroll
        for (int c = 0; c < NCHUNK; c++) {
            ulonglong2 bv2 = bov[(c*16 + l4)*32 + lane];  // LDS.128
#pragma unroll
            for (int q = 0; q < QPW; q++) {
                float f0, f1, f2, f3;
                upk(add2(a01[q], bv2.x), f0, f1);
                upk(add2(a23[q], bv2.y), f2, f3);
                float t = lacc[q*NCHUNK + c];
                t = fmaf(w.x, fabsf(f0), t);
                t = fmaf(w.y, fabsf(f1), t);
                t = fmaf(w.z, fabsf(f2), t);
                t = fmaf(w.w, fabsf(f3), t);
                lacc[q*NCHUNK + c] = t;
            }
        }
    }

    // ---- assemble logits + radius mask ----
    const float* s_oc  = (const float*)(sm + SOC);
    const float* s_qac = (const float*)(sm + SQAC);
    const float4* s_pos = (const float4*)(sm + SPOS);

    float lg[QPW*NCHUNK];
#pragma unroll
    for (int c = 0; c < NCHUNK; c++) {
        float4 po = s_pos[c*32 + lane];
        float oc  = s_oc[c*32 + lane];
#pragma unroll
        for (int q = 0; q < QPW; q++) {
            float dx = qpx[q] - po.x, dy = qpy[q] - po.y, dz = qpz[q] - po.z;
            float d2 = fmaf(dx, dx, fmaf(dy, dy, dz*dz));
            float l = s_qac[q0+q] + oc + lacc[q*NCHUNK + c];
            lg[q*NCHUNK + c] = (d2 <= 0.25f) ? l : NEGBIG;
        }
    }

    // ---- single-pass softmax stats; p overwrites lg ----
    float m[QPW], s[QPW];
#pragma unroll
    for (int q = 0; q < QPW; q++) {
        float cm = fmaxf(fmaxf(lg[q*NCHUNK], lg[q*NCHUNK+1]),
                         fmaxf(lg[q*NCHUNK+2], lg[q*NCHUNK+3]));
#pragma unroll
        for (int off = 16; off > 0; off >>= 1)
            cm = fmaxf(cm, __shfl_xor_sync(FULLMASK, cm, off));
        m[q] = cm;
        float sl = 0.f;
#pragma unroll
        for (int c = 0; c < NCHUNK; c++) {
            float pe = exp2f((lg[q*NCHUNK+c] - cm) * L2E);
            lg[q*NCHUNK+c] = pe;
            sl += pe;
        }
        s[q] = sl;
    }

    __syncthreads();   // all b-reads done: SBO region now reusable as s_p

    // ---- P*V: publish all p once (warp-private 4KB of dead SBO) ----
    float4* wp4 = (float4*)(sm + SBO + warp*4096);
#pragma unroll
    for (int c = 0; c < NCHUNK; c++) {
        wp4[(c*32 + lane)*2 + 0] = make_float4(lg[0*NCHUNK+c], lg[0*NCHUNK+c],
                                               lg[1*NCHUNK+c], lg[1*NCHUNK+c]);
        wp4[(c*32 + lane)*2 + 1] = make_float4(lg[2*NCHUNK+c], lg[2*NCHUNK+c],
                                               lg[3*NCHUNK+c], lg[3*NCHUNK+c]);
    }
    __syncwarp();

    u64 acc[QPW];
#pragma unroll
    for (int q = 0; q < QPW; q++) acc[q] = 0ULL;

    const u64* vvb        = (const u64*)(sm + SV) + lane;
    const ulonglong2* wpu = (const ulonglong2*)wp4;
#pragma unroll 2
    for (int o = 0; o < OPART; o++) {
        u64 vv2 = vvb[o*32];                 // LDS.64
        ulonglong2 pA = wpu[o*2 + 0];        // LDS.128 broadcast {p0,p0},{p1,p1}
        ulonglong2 pB = wpu[o*2 + 1];        // LDS.128 broadcast {p2,p2},{p3,p3}
        acc[0] = fma2(pA.x, vv2, acc[0]);
        acc[1] = fma2(pA.y, vv2, acc[1]);
        acc[2] = fma2(pB.x, vv2, acc[2]);
        acc[3] = fma2(pB.y, vv2, acc[3]);
    }

    // ---- partial epilogue ----
#pragma unroll
    for (int q = 0; q < QPW; q++) {
        float sl = s[q];
#pragma unroll
        for (int off = 16; off > 0; off >>= 1)
            sl += __shfl_xor_sync(FULLMASK, sl, off);
        int gq = gq0 + q;
        float lo, hi; upk(acc[q], lo, hi);
        ((float2*)&g_pacc[split][gq*LAT])[lane] = make_float2(lo, hi);
        if (lane == 0) { g_pm[split][gq] = m[q]; g_ps[split][gq] = sl; }
    }
}

// ---------------- combine the OSPLIT partials ----------------
__global__ void combine_kernel(float* __restrict__ out)
{
    int gid = blockIdx.x * blockDim.x + threadIdx.x;   // NQ*32
    int q  = gid >> 5;
    int l2 = gid & 31;

    float M = NEGBIG;
#pragma unroll
    for (int sp = 0; sp < OSPLIT; sp++) M = fmaxf(M, g_pm[sp][q]);

    float denom = 0.f;
    float rx = 0.f, ry = 0.f;
#pragma unroll
    for (int sp = 0; sp < OSPLIT; sp++) {
        float w = exp2f((g_pm[sp][q] - M) * L2E);
        denom = fmaf(g_ps[sp][q], w, denom);
        float2 a = ((const float2*)&g_pacc[sp][q*LAT])[l2];
        rx = fmaf(a.x, w, rx);
        ry = fmaf(a.y, w, ry);
    }
    float inv = 1.f / denom;
    ((float2*)out)[gid] = make_float2(rx * inv, ry * inv);
}

// ---------------- launch ----------------
extern "C" void kernel_launch(void* const* d_in, const int* in_sizes, int n_in,
                              void* d_out, int out_size)
{
    const float* h_obs     = (const float*)d_in[0];
    // d_in[1] = x_obs (unused by reference)
    const float* pos_obs   = (const float*)d_in[2];
    const float* pos_query = (const float*)d_in[3];
    const float* W1        = (const float*)d_in[4];
    const float* b1        = (const float*)d_in[5];
    const float* W2        = (const float*)d_in[6];
    // d_in[7] = b2 — cancels in softmax
    const float* Wv        = (const float*)d_in[8];
    const float* bv        = (const float*)d_in[9];

    cudaFuncSetAttribute(main_kernel,
                         cudaFuncAttributeMaxDynamicSharedMemorySize, SMEM_BYTES);

    prep_kernel<<<128 + (NQ*LAT)/256, 256>>>(h_obs, pos_obs, pos_query, W1, b1, W2, Wv, bv);

    dim3 grid(NQ/QPB, OSPLIT);
    main_kernel<<<grid, THREADS, SMEM_BYTES>>>(pos_query);

    combine_kernel<<<(NQ*32)/256, 256>>>((float*)d_out);
}

// round 12
// speedup vs baseline: 1.0006x; 1.0006x over previous
#include <cuda_runtime.h>

#define NQ 2048
#define NO 2048
#define LAT 64
#define OSPLIT 16
#define QPW 4
#define NWARPS 8
#define QPB (QPW*NWARPS)      /* 32 queries per block */
#define THREADS (NWARPS*32)   /* 256 */
#define OPART (NO/OSPLIT)     /* 128 obs per block */
#define NCHUNK 4              /* 4 chunks of 32 within OPART */
#define L2E 1.4426950408889634f
#define NEGBIG (-1e30f)
#define FULLMASK 0xffffffffu

typedef unsigned long long u64;

// dynamic smem layout (bytes)
#define SV    0        /* float s_v[128*64]            32768 */
#define SBO   32768    /* float4 s_bo[4][16][32]       32768 (aliased by s_p after logits) */
#define SAQ   65536    /* float4 s_aq[32][16]           8192 */
#define SPOS  73728    /* float4 s_pos[128]             2048 */
#define SW2H  75776    /* float4 s_w2h[16]               256 */
#define SOC   76032    /* float  s_oc[128]               512 */
#define SQAC  76544    /* float  s_qac[32]               128 */
#define SMEM_BYTES 76672

// ---------------- packed f32x2 helpers ----------------
__device__ __forceinline__ void upk(u64 v, float& lo, float& hi) {
    asm("mov.b64 {%0,%1},%2;" : "=f"(lo), "=f"(hi) : "l"(v));
}
__device__ __forceinline__ u64 add2(u64 a, u64 b) {
    u64 d; asm("add.rn.f32x2 %0,%1,%2;" : "=l"(d) : "l"(a), "l"(b)); return d;
}
__device__ __forceinline__ u64 fma2(u64 a, u64 b, u64 c) {
    u64 d; asm("fma.rn.f32x2 %0,%1,%2,%3;" : "=l"(d) : "l"(a), "l"(b), "l"(c)); return d;
}

// ---------------- cp.async helpers ----------------
__device__ __forceinline__ void cpa16(void* smem, const void* g) {
    unsigned s = (unsigned)__cvta_generic_to_shared(smem);
    asm volatile("cp.async.cg.shared.global [%0], [%1], 16;" :: "r"(s), "l"(g));
}
#define CP_COMMIT() asm volatile("cp.async.commit_group;")
#define CP_WAIT0()  asm volatile("cp.async.wait_group 0;")

// ---------------- device scratch ----------------
__device__ float4 g_aq4[NQ*LAT/4];      // [q][l4]
__device__ float4 g_bo4[NO*LAT/4];      // interleaved [gchunk][l4][o_in32]
__device__ float4 g_v4[NO*LAT/4];       // [o][l4]
__device__ float4 g_pos4[NO];           // (x,y,z,0)
__device__ float  g_qac[NQ];            // sum_l w2h*aq
__device__ float  g_obc[NO];            // sum_l w2h*bo
__device__ float  g_w2h[LAT];           // W2*0.5
__device__ float  g_pacc[OSPLIT][NQ*LAT];
__device__ float  g_pm[OSPLIT][NQ];
__device__ float  g_ps[OSPLIT][NQ];

// ---------------- prep ----------------
__global__ __launch_bounds__(256)
void prep_kernel(const float* __restrict__ h_obs,
                 const float* __restrict__ pos_obs,
                 const float* __restrict__ pos_query,
                 const float* __restrict__ W1,
                 const float* __restrict__ b1,
                 const float* __restrict__ W2,
                 const float* __restrict__ Wv,
                 const float* __restrict__ bv)
{
    __shared__ float4 s_wv[64*16];   // 16KB (v branch)
    __shared__ float4 s_bv[16];
    __shared__ float  spa[8], spb[8];
    const int tid = threadIdx.x;
    const int blk = blockIdx.x;

    if (blk < 128) {
        const float4* wv4 = (const float4*)Wv;
#pragma unroll
        for (int i = 0; i < 4; i++) s_wv[i*256 + tid] = wv4[i*256 + tid];
        if (tid < 16) s_bv[tid] = ((const float4*)bv)[tid];
        __syncthreads();

        const int l4  = tid & 15;
        const int r   = tid >> 4;
        const int row = blk*16 + r;
        const float4* h4 = (const float4*)(h_obs + row*LAT);

        float4 a0 = s_bv[l4];
        float4 a1 = make_float4(0.f,0.f,0.f,0.f);
        float4 a2 = make_float4(0.f,0.f,0.f,0.f);
        float4 a3 = make_float4(0.f,0.f,0.f,0.f);
#pragma unroll
        for (int k4 = 0; k4 < 16; k4++) {
            float4 h = h4[k4];
            float4 w0 = s_wv[(4*k4+0)*16 + l4];
            float4 w1 = s_wv[(4*k4+1)*16 + l4];
            float4 w2 = s_wv[(4*k4+2)*16 + l4];
            float4 w3 = s_wv[(4*k4+3)*16 + l4];
            a0.x = fmaf(h.x, w0.x, a0.x); a0.y = fmaf(h.x, w0.y, a0.y);
            a0.z = fmaf(h.x, w0.z, a0.z); a0.w = fmaf(h.x, w0.w, a0.w);
            a1.x = fmaf(h.y, w1.x, a1.x); a1.y = fmaf(h.y, w1.y, a1.y);
            a1.z = fmaf(h.y, w1.z, a1.z); a1.w = fmaf(h.y, w1.w, a1.w);
            a2.x = fmaf(h.z, w2.x, a2.x); a2.y = fmaf(h.z, w2.y, a2.y);
            a2.z = fmaf(h.z, w2.z, a2.z); a2.w = fmaf(h.z, w2.w, a2.w);
            a3.x = fmaf(h.w, w3.x, a3.x); a3.y = fmaf(h.w, w3.y, a3.y);
            a3.z = fmaf(h.w, w3.z, a3.z); a3.w = fmaf(h.w, w3.w, a3.w);
        }
        float4 v;
        v.x = (a0.x + a1.x) + (a2.x + a3.x);
        v.y = (a0.y + a1.y) + (a2.y + a3.y);
        v.z = (a0.z + a1.z) + (a2.z + a3.z);
        v.w = (a0.w + a1.w) + (a2.w + a3.w);
        g_v4[row*16 + l4] = v;
    } else {
        int idx = (blk - 128)*256 + tid;     // covers NQ*LAT
        int row = idx >> 6;
        int l   = idx & 63;

        float a = 0.f;
        float b = b1[l];
#pragma unroll
        for (int e = 0; e < 3; e++) {
            float wc = W1[(6+e)*LAT + l];
            a = fmaf(pos_query[row*3 + e], W1[e*LAT + l] + wc, a);
            b = fmaf(pos_obs  [row*3 + e], W1[(3+e)*LAT + l] - wc, b);
        }
        ((float*)g_aq4)[row*LAT + l] = a;

        int ch = row >> 5, oin = row & 31, l4i = l >> 2, li = l & 3;
        ((float*)g_bo4)[(((ch*16) + l4i)*32 + oin)*4 + li] = b;

        if (l == 0)
            g_pos4[row] = make_float4(pos_obs[row*3], pos_obs[row*3+1], pos_obs[row*3+2], 0.f);

        // w2h-weighted row reductions
        float w2h = 0.5f * W2[l];
        float ta = w2h * a, tb = w2h * b;
#pragma unroll
        for (int off = 16; off > 0; off >>= 1) {
            ta += __shfl_xor_sync(FULLMASK, ta, off);
            tb += __shfl_xor_sync(FULLMASK, tb, off);
        }
        int wl = tid >> 5;
        if ((tid & 31) == 0) { spa[wl] = ta; spb[wl] = tb; }
        __syncthreads();
        if ((tid & 63) == 0) {
            g_qac[row] = spa[wl] + spa[wl+1];
            g_obc[row] = spb[wl] + spb[wl+1];
        }
        if (blk == 128 && tid < 64)
            g_w2h[tid] = 0.5f * W2[tid];
    }
}

// ---------------- main: fused masked-softmax attention ----------------
__global__ __launch_bounds__(THREADS, 3)
void main_kernel(const float* __restrict__ pos_query)
{
    extern __shared__ char sm[];
    const int tid   = threadIdx.x;
    const int warp  = tid >> 5;
    const int lane  = tid & 31;
    const int qblk  = blockIdx.x;        // 0..63
    const int split = blockIdx.y;        // 0..15
    const int obase = split * OPART;
    const int gch0  = obase / 32;

    // ---- prologue: one-shot async staging of all tiles ----
    {
        float4* sv = (float4*)(sm + SV);
        float4* sb = (float4*)(sm + SBO);
        const float4* gv = g_v4  + obase*16;
        const float4* gb = g_bo4 + gch0*512;
#pragma unroll
        for (int i = 0; i < 8; i++) {
            cpa16(&sv[i*THREADS + tid], &gv[i*THREADS + tid]);
            cpa16(&sb[i*THREADS + tid], &gb[i*THREADS + tid]);
        }
        float4* sa = (float4*)(sm + SAQ);
        const float4* ga = g_aq4 + qblk*QPB*16;
#pragma unroll
        for (int i = 0; i < 2; i++)
            cpa16(&sa[i*THREADS + tid], &ga[i*THREADS + tid]);
        if (tid < 128) cpa16(&((float4*)(sm + SPOS))[tid], &g_pos4[obase + tid]);
        if (tid < 16)  cpa16(&((float4*)(sm + SW2H))[tid], &((const float4*)g_w2h)[tid]);
        if (tid < 32)  cpa16((float*)(sm + SOC) + tid*4, &g_obc[obase + tid*4]);
        if (tid < 8)   cpa16((float*)(sm + SQAC) + tid*4, &g_qac[qblk*QPB + tid*4]);
        CP_COMMIT();
    }

    // per-warp query constants (broadcast global loads, L1/L2-resident)
    const int q0  = warp*QPW;
    const int gq0 = qblk*QPB + q0;
    float qpx[QPW], qpy[QPW], qpz[QPW];
#pragma unroll
    for (int q = 0; q < QPW; q++) {
        qpx[q] = pos_query[(gq0+q)*3 + 0];
        qpy[q] = pos_query[(gq0+q)*3 + 1];
        qpz[q] = pos_query[(gq0+q)*3 + 2];
    }

    CP_WAIT0();
    __syncthreads();

    // ---- logits for all 128 obs: LDS.128 as ulonglong2 (no pk MOVs) ----
    float lacc[QPW*NCHUNK];
#pragma unroll
    for (int i = 0; i < QPW*NCHUNK; i++) lacc[i] = 0.f;

    const ulonglong2* aqv  = (const ulonglong2*)(sm + SAQ);
    const ulonglong2* bov  = (const ulonglong2*)(sm + SBO);
    const float4*     w2h4 = (const float4*)(sm + SW2H);

#pragma unroll 1
    for (int l4 = 0; l4 < 16; l4++) {
        float4 w = w2h4[l4];
        u64 a01[QPW], a23[QPW];
#pragma unroll
        for (int q = 0; q < QPW; q++) {
            ulonglong2 av = aqv[(q0+q)*16 + l4];   // LDS.128 broadcast
            a01[q] = av.x;
            a23[q] = av.y;
        }
#pragma unroll
        for (int c = 0; c < NCHUNK; c++) {
            ulonglong2 bv2 = bov[(c*16 + l4)*32 + lane];  // LDS.128
#pragma unroll
            for (int q = 0; q < QPW; q++) {
                float f0, f1, f2, f3;
                upk(add2(a01[q], bv2.x), f0, f1);
                upk(add2(a23[q], bv2.y), f2, f3);
                float t = lacc[q*NCHUNK + c];
                t = fmaf(w.x, fabsf(f0), t);
                t = fmaf(w.y, fabsf(f1), t);
                t = fmaf(w.z, fabsf(f2), t);
                t = fmaf(w.w, fabsf(f3), t);
                lacc[q*NCHUNK + c] = t;
            }
        }
    }

    // ---- assemble logits + radius mask ----
    const float* s_oc  = (const float*)(sm + SOC);
    const float* s_qac = (const float*)(sm + SQAC);
    const float4* s_pos = (const float4*)(sm + SPOS);

    float lg[QPW*NCHUNK];
#pragma unroll
    for (int c = 0; c < NCHUNK; c++) {
        float4 po = s_pos[c*32 + lane];
        float oc  = s_oc[c*32 + lane];
#pragma unroll
        for (int q = 0; q < QPW; q++) {
            float dx = qpx[q] - po.x, dy = qpy[q] - po.y, dz = qpz[q] - po.z;
            float d2 = fmaf(dx, dx, fmaf(dy, dy, dz*dz));
            float l = s_qac[q0+q] + oc + lacc[q*NCHUNK + c];
            lg[q*NCHUNK + c] = (d2 <= 0.25f) ? l : NEGBIG;
        }
    }

    // ---- single-pass softmax stats; p overwrites lg ----
    float m[QPW], s[QPW];
#pragma unroll
    for (int q = 0; q < QPW; q++) {
        float cm = fmaxf(fmaxf(lg[q*NCHUNK], lg[q*NCHUNK+1]),
                         fmaxf(lg[q*NCHUNK+2], lg[q*NCHUNK+3]));
#pragma unroll
        for (int off = 16; off > 0; off >>= 1)
            cm = fmaxf(cm, __shfl_xor_sync(FULLMASK, cm, off));
        m[q] = cm;
        float sl = 0.f;
#pragma unroll
        for (int c = 0; c < NCHUNK; c++) {
            float pe = exp2f((lg[q*NCHUNK+c] - cm) * L2E);
            lg[q*NCHUNK+c] = pe;
            sl += pe;
        }
        s[q] = sl;
    }

    __syncthreads();   // all b-reads done: SBO region now reusable as s_p

    // ---- P*V: publish all p once (warp-private 4KB of dead SBO) ----
    float4* wp4 = (float4*)(sm + SBO + warp*4096);
#pragma unroll
    for (int c = 0; c < NCHUNK; c++) {
        wp4[(c*32 + lane)*2 + 0] = make_float4(lg[0*NCHUNK+c], lg[0*NCHUNK+c],
                                               lg[1*NCHUNK+c], lg[1*NCHUNK+c]);
        wp4[(c*32 + lane)*2 + 1] = make_float4(lg[2*NCHUNK+c], lg[2*NCHUNK+c],
                                               lg[3*NCHUNK+c], lg[3*NCHUNK+c]);
    }
    __syncwarp();

    u64 acc[QPW];
#pragma unroll
    for (int q = 0; q < QPW; q++) acc[q] = 0ULL;

    const u64* vvb        = (const u64*)(sm + SV) + lane;
    const ulonglong2* wpu = (const ulonglong2*)wp4;
#pragma unroll 2
    for (int o = 0; o < OPART; o++) {
        u64 vv2 = vvb[o*32];                 // LDS.64
        ulonglong2 pA = wpu[o*2 + 0];        // LDS.128 broadcast {p0,p0},{p1,p1}
        ulonglong2 pB = wpu[o*2 + 1];        // LDS.128 broadcast {p2,p2},{p3,p3}
        acc[0] = fma2(pA.x, vv2, acc[0]);
        acc[1] = fma2(pA.y, vv2, acc[1]);
        acc[2] = fma2(pB.x, vv2, acc[2]);
        acc[3] = fma2(pB.y, vv2, acc[3]);
    }

    // ---- partial epilogue ----
#pragma unroll
    for (int q = 0; q < QPW; q++) {
        float sl = s[q];
#pragma unroll
        for (int off = 16; off > 0; off >>= 1)
            sl += __shfl_xor_sync(FULLMASK, sl, off);
        int gq = gq0 + q;
        float lo, hi; upk(acc[q], lo, hi);
        ((float2*)&g_pacc[split][gq*LAT])[lane] = make_float2(lo, hi);
        if (lane == 0) { g_pm[split][gq] = m[q]; g_ps[split][gq] = sl; }
    }
}

// ---------------- combine the OSPLIT partials ----------------
__global__ void combine_kernel(float* __restrict__ out)
{
    int gid = blockIdx.x * blockDim.x + threadIdx.x;   // NQ*32
    int q  = gid >> 5;
    int l2 = gid & 31;

    float M = NEGBIG;
#pragma unroll
    for (int sp = 0; sp < OSPLIT; sp++) M = fmaxf(M, g_pm[sp][q]);

    float denom = 0.f;
    float rx = 0.f, ry = 0.f;
#pragma unroll
    for (int sp = 0; sp < OSPLIT; sp++) {
        float w = exp2f((g_pm[sp][q] - M) * L2E);
        denom = fmaf(g_ps[sp][q], w, denom);
        float2 a = ((const float2*)&g_pacc[sp][q*LAT])[l2];
        rx = fmaf(a.x, w, rx);
        ry = fmaf(a.y, w, ry);
    }
    float inv = 1.f / denom;
    ((float2*)out)[gid] = make_float2(rx * inv, ry * inv);
}

// ---------------- launch ----------------
extern "C" void kernel_launch(void* const* d_in, const int* in_sizes, int n_in,
                              void* d_out, int out_size)
{
    const float* h_obs     = (const float*)d_in[0];
    // d_in[1] = x_obs (unused by reference)
    const float* pos_obs   = (const float*)d_in[2];
    const float* pos_query = (const float*)d_in[3];
    const float* W1        = (const float*)d_in[4];
    const float* b1        = (const float*)d_in[5];
    const float* W2        = (const float*)d_in[6];
    // d_in[7] = b2 — cancels in softmax
    const float* Wv        = (const float*)d_in[8];
    const float* bv        = (const float*)d_in[9];

    cudaFuncSetAttribute(main_kernel,
                         cudaFuncAttributeMaxDynamicSharedMemorySize, SMEM_BYTES);

    prep_kernel<<<128 + (NQ*LAT)/256, 256>>>(h_obs, pos_obs, pos_query, W1, b1, W2, Wv, bv);

    dim3 grid(NQ/QPB, OSPLIT);
    main_kernel<<<grid, THREADS, SMEM_BYTES>>>(pos_query);

    combine_kernel<<<(NQ*32)/256, 256>>>((float*)d_out);
}